// round 1
// baseline (speedup 1.0000x reference)
#include <cuda_runtime.h>

#define NMAX 50000
#define EMAX 800000
#define GMAX 2500
#define ETOT (EMAX + NMAX)

// ---------------- scratch (device globals; no allocation allowed) ----------------
__device__ float g_h[NMAX * 128];      // per-layer hidden [N, 2*64]
__device__ float g_f0[NMAX * 64];      // layer output ping
__device__ float g_f1[NMAX * 64];      // layer output pong
__device__ float g_att[NMAX * 4];      // per node: a_src0, a_src1, a_dst0, a_dst1
__device__ int   g_rp[NMAX + 1];       // CSR row_ptr by dst
__device__ int   g_deg[NMAX];
__device__ int   g_fill[NMAX];
__device__ int   g_csrc[ETOT];         // CSR src indices
__device__ float g_gsum[GMAX];
__device__ float g_gcnt[GMAX];

// ---------------- CSR build (dst is layer-invariant: build once per call) -------
__global__ void k_init_deg(int n) {
  int i = blockIdx.x * blockDim.x + threadIdx.x;
  if (i < n) { g_deg[i] = 1; g_fill[i] = 0; }   // 1 = self loop
}

__global__ void k_count(const int* __restrict__ ei, int E) {
  int i = blockIdx.x * blockDim.x + threadIdx.x;
  if (i < E) atomicAdd(&g_deg[ei[E + i]], 1);   // dst row of edge_index
}

__global__ void k_scan(int n) {
  __shared__ int sums[1024];
  int t = threadIdx.x;
  int chunk = (n + 1023) / 1024;
  int b = t * chunk;
  int e = min(b + chunk, n);
  int s = 0;
  for (int i = b; i < e; i++) s += g_deg[i];
  sums[t] = s;
  __syncthreads();
  for (int o = 1; o < 1024; o <<= 1) {
    int v = (t >= o) ? sums[t - o] : 0;
    __syncthreads();
    sums[t] += v;
    __syncthreads();
  }
  int run = sums[t] - s;   // exclusive prefix
  for (int i = b; i < e; i++) { g_rp[i] = run; run += g_deg[i]; }
  if (t == 1023) g_rp[n] = sums[1023];
}

__global__ void k_scatter(const int* __restrict__ ei, int E, int n) {
  int i = blockIdx.x * blockDim.x + threadIdx.x;
  if (i >= E + n) return;
  int s, d;
  if (i < E) { s = ei[i]; d = ei[E + i]; } else { s = d = i - E; }
  int pos = atomicAdd(&g_fill[d], 1);
  g_csrc[g_rp[d] + pos] = s;
}

// ---------------- GEMM: h[N,128] = X[N,fin] @ W[fin,128] ------------------------
// block = 128 threads, 32-row tile in smem, 8 rows x 4 cols register blocking.
__global__ void k_gemm(const float* __restrict__ Xin, int insel,
                       const float* __restrict__ W, int n, int fin) {
  const float* X = Xin ? Xin : (insel ? g_f1 : g_f0);
  __shared__ float xs[32 * 128];
  int tid = threadIdx.x;
  int row0 = blockIdx.x * 32;
  int fin4 = fin >> 2;
  int nf4 = 32 * fin4;
  const float4* X4 = (const float4*)X;
  for (int i = tid; i < nf4; i += 128) {
    int row = i / fin4;
    int kk = i - row * fin4;
    float4 v = make_float4(0.f, 0.f, 0.f, 0.f);
    if (row0 + row < n) v = X4[(row0 + row) * fin4 + kk];
    ((float4*)xs)[i] = v;
  }
  __syncthreads();
  int colg = tid & 31;
  int rowseg = tid >> 5;
  float acc[8][4];
#pragma unroll
  for (int r = 0; r < 8; r++) { acc[r][0] = acc[r][1] = acc[r][2] = acc[r][3] = 0.f; }
  const float* xb = &xs[(rowseg * 8) * fin];
  for (int k = 0; k < fin; k++) {
    float4 w = *(const float4*)&W[k * 128 + colg * 4];
#pragma unroll
    for (int r = 0; r < 8; r++) {
      float x = xb[r * fin + k];
      acc[r][0] += x * w.x; acc[r][1] += x * w.y;
      acc[r][2] += x * w.z; acc[r][3] += x * w.w;
    }
  }
#pragma unroll
  for (int r = 0; r < 8; r++) {
    int row = row0 + rowseg * 8 + r;
    if (row < n)
      *(float4*)&g_h[row * 128 + colg * 4] =
          make_float4(acc[r][0], acc[r][1], acc[r][2], acc[r][3]);
  }
}

// ---------------- attention coefficients per node --------------------------------
__global__ void k_att(const float* __restrict__ asrc, const float* __restrict__ adst, int n) {
  int w = blockIdx.x * 8 + (threadIdx.x >> 5);
  int lane = threadIdx.x & 31;
  if (w >= n) return;
  const float* hp = &g_h[w * 128];
  float h0 = hp[lane], h1 = hp[lane + 32], h2 = hp[lane + 64], h3 = hp[lane + 96];
  float ps0 = h0 * asrc[lane]      + h1 * asrc[lane + 32];
  float ps1 = h2 * asrc[64 + lane] + h3 * asrc[96 + lane];
  float pd0 = h0 * adst[lane]      + h1 * adst[lane + 32];
  float pd1 = h2 * adst[64 + lane] + h3 * adst[96 + lane];
#pragma unroll
  for (int o = 16; o; o >>= 1) {
    ps0 += __shfl_xor_sync(0xffffffffu, ps0, o);
    ps1 += __shfl_xor_sync(0xffffffffu, ps1, o);
    pd0 += __shfl_xor_sync(0xffffffffu, pd0, o);
    pd1 += __shfl_xor_sync(0xffffffffu, pd1, o);
  }
  if (lane == 0) *(float4*)&g_att[4 * w] = make_float4(ps0, ps1, pd0, pd1);
}

// ---------------- softmax + aggregate + head-mean + bias + relu ------------------
// one warp per destination node; pass1 lane-parallel max; pass2 serial edge loop,
// lanes = channels (4 coalesced 128B row loads per edge), exp recomputed in-warp,
// 1/sum folded into epilogue.
__global__ void k_agg(const float* __restrict__ bias, int outsel, int n) {
  float* OUT = outsel ? g_f1 : g_f0;
  int v = blockIdx.x * 8 + (threadIdx.x >> 5);
  int lane = threadIdx.x & 31;
  if (v >= n) return;
  int rs = g_rp[v], re = g_rp[v + 1];
  float ad0 = g_att[4 * v + 2], ad1 = g_att[4 * v + 3];

  float m0 = -1e30f, m1 = -1e30f;
  for (int j = rs + lane; j < re; j += 32) {
    int s = g_csrc[j];
    float2 as = *(const float2*)&g_att[4 * s];
    float e0 = as.x + ad0; e0 = e0 > 0.f ? e0 : 0.2f * e0;
    float e1 = as.y + ad1; e1 = e1 > 0.f ? e1 : 0.2f * e1;
    m0 = fmaxf(m0, e0); m1 = fmaxf(m1, e1);
  }
#pragma unroll
  for (int o = 16; o; o >>= 1) {
    m0 = fmaxf(m0, __shfl_xor_sync(0xffffffffu, m0, o));
    m1 = fmaxf(m1, __shfl_xor_sync(0xffffffffu, m1, o));
  }

  float s0 = 0.f, s1 = 0.f;
  float a0 = 0.f, a1 = 0.f, a2 = 0.f, a3 = 0.f;
  for (int j = rs; j < re; j++) {
    int s = g_csrc[j];                                  // warp-broadcast load
    float2 as = *(const float2*)&g_att[4 * s];          // warp-broadcast load
    float e0 = as.x + ad0; e0 = e0 > 0.f ? e0 : 0.2f * e0;
    float e1 = as.y + ad1; e1 = e1 > 0.f ? e1 : 0.2f * e1;
    float x0 = __expf(e0 - m0), x1 = __expf(e1 - m1);
    s0 += x0; s1 += x1;
    const float* hp = &g_h[s * 128];
    a0 += hp[lane]      * x0;
    a1 += hp[lane + 32] * x0;
    a2 += hp[lane + 64] * x1;
    a3 += hp[lane + 96] * x1;
  }
  float r0 = 1.f / fmaxf(s0, 1e-16f);
  float r1 = 1.f / fmaxf(s1, 1e-16f);
  float o1 = 0.5f * (a0 * r0 + a2 * r1) + bias[lane];
  float o2 = 0.5f * (a1 * r0 + a3 * r1) + bias[lane + 32];
  OUT[v * 64 + lane]      = fmaxf(o1, 0.f);
  OUT[v * 64 + lane + 32] = fmaxf(o2, 0.f);
}

// ---------------- pooling + final linear -----------------------------------------
__global__ void k_zero_pool(int g) {
  int i = blockIdx.x * blockDim.x + threadIdx.x;
  if (i < g) { g_gsum[i] = 0.f; g_gcnt[i] = 0.f; }
}

__global__ void k_pool(const float* __restrict__ lw, const int* __restrict__ batch, int n) {
  int v = blockIdx.x * 8 + (threadIdx.x >> 5);
  int lane = threadIdx.x & 31;
  if (v >= n) return;
  const float* fp = &g_f0[v * 64];
  float p = fp[lane] * lw[lane] + fp[lane + 32] * lw[lane + 32];
#pragma unroll
  for (int o = 16; o; o >>= 1) p += __shfl_xor_sync(0xffffffffu, p, o);
  if (lane == 0) {
    int b = batch[v];
    atomicAdd(&g_gsum[b], p);
    atomicAdd(&g_gcnt[b], 1.f);
  }
}

__global__ void k_final(const float* __restrict__ lb, float* __restrict__ out, int g) {
  int i = blockIdx.x * blockDim.x + threadIdx.x;
  if (i < g) out[i] = g_gsum[i] / fmaxf(g_gcnt[i], 1.f) + lb[0];
}

// ---------------- launch ----------------------------------------------------------
extern "C" void kernel_launch(void* const* d_in, const int* in_sizes, int n_in,
                              void* d_out, int out_size) {
  // Detect input ordering: dict order (x, edge_index, batch, weights...) vs
  // reference-signature order (x, weights..., edge_index, batch).
  int base;
  const int *ei, *bat;
  int Esz;
  if (in_sizes[1] > 1000000) {          // edge_index (2*E ints) at slot 1
    ei = (const int*)d_in[1];
    bat = (const int*)d_in[2];
    base = 3;
    Esz = in_sizes[1];
  } else {                               // signature order
    base = 1;
    ei = (const int*)d_in[15];
    bat = (const int*)d_in[16];
    Esz = in_sizes[15];
  }
  const float* x   = (const float*)d_in[0];
  const float* W1  = (const float*)d_in[base + 0];
  const float* as1 = (const float*)d_in[base + 1];
  const float* ad1 = (const float*)d_in[base + 2];
  const float* b1  = (const float*)d_in[base + 3];
  const float* W2  = (const float*)d_in[base + 4];
  const float* as2 = (const float*)d_in[base + 5];
  const float* ad2 = (const float*)d_in[base + 6];
  const float* b2  = (const float*)d_in[base + 7];
  const float* W3  = (const float*)d_in[base + 8];
  const float* as3 = (const float*)d_in[base + 9];
  const float* ad3 = (const float*)d_in[base + 10];
  const float* b3  = (const float*)d_in[base + 11];
  const float* lw  = (const float*)d_in[base + 12];
  const float* lb  = (const float*)d_in[base + 13];

  int n = in_sizes[0] / 128;
  int E = Esz / 2;
  int G = out_size;

  const int tb = 256;
  // CSR build (dst-grouped; identical across layers)
  k_init_deg<<<(n + tb - 1) / tb, tb>>>(n);
  k_count<<<(E + tb - 1) / tb, tb>>>(ei, E);
  k_scan<<<1, 1024>>>(n);
  k_scatter<<<(E + n + tb - 1) / tb, tb>>>(ei, E, n);

  int gb = (n + 31) / 32;
  int wg = (n + 7) / 8;

  // layer 1: x[N,128] -> f0
  k_gemm<<<gb, 128>>>(x, 0, W1, n, 128);
  k_att<<<wg, 256>>>(as1, ad1, n);
  k_agg<<<wg, 256>>>(b1, 0, n);
  // layer 2: f0 -> f1
  k_gemm<<<gb, 128>>>(nullptr, 0, W2, n, 64);
  k_att<<<wg, 256>>>(as2, ad2, n);
  k_agg<<<wg, 256>>>(b2, 1, n);
  // layer 3: f1 -> f0
  k_gemm<<<gb, 128>>>(nullptr, 1, W3, n, 64);
  k_att<<<wg, 256>>>(as3, ad3, n);
  k_agg<<<wg, 256>>>(b3, 0, n);

  // pool + linear
  k_zero_pool<<<(G + tb - 1) / tb, tb>>>(G);
  k_pool<<<wg, 256>>>(lw, bat, n);
  k_final<<<(G + tb - 1) / tb, tb>>>(lb, (float*)d_out, G);
}

// round 2
// speedup vs baseline: 1.3208x; 1.3208x over previous
#include <cuda_runtime.h>

#define NMAX 50000
#define EMAX 800000
#define GMAX 2500
#define ETOT (EMAX + NMAX)

// packed dual-fp32 helpers (sm_100+ PTX)
#define PACK2(out, f) asm("mov.b64 %0, {%1, %1};" : "=l"(out) : "r"(__float_as_uint(f)))
#define FMA2(d, a, b) asm("fma.rn.f32x2 %0, %1, %2, %0;" : "+l"(d) : "l"(a), "l"(b))
#define UNPACK2(lo, hi, v) asm("mov.b64 {%0, %1}, %2;" : "=r"(lo), "=r"(hi) : "l"(v))

// ---------------- scratch (device globals; no allocation allowed) ----------------
__device__ float g_h[NMAX * 128];      // per-layer hidden [N, 2*64]
__device__ float g_f0[NMAX * 64];      // layer output ping
__device__ float g_f1[NMAX * 64];      // layer output pong
__device__ float g_att[NMAX * 4];      // per node: a_src0, a_src1, a_dst0, a_dst1
__device__ int   g_rp[NMAX + 1];       // CSR row_ptr by dst
__device__ int   g_deg[NMAX];
__device__ int   g_fill[NMAX];
__device__ int   g_csrc[ETOT];         // CSR src indices
__device__ float g_gsum[GMAX];
__device__ float g_gcnt[GMAX];

// ---------------- CSR build (dst is layer-invariant) + pool zeroing --------------
__global__ void k_init(int n, int g) {
  int i = blockIdx.x * blockDim.x + threadIdx.x;
  if (i < n) { g_deg[i] = 1; g_fill[i] = 0; }   // 1 = self loop
  if (i < g) { g_gsum[i] = 0.f; g_gcnt[i] = 0.f; }
}

__global__ void k_count(const int* __restrict__ ei, int E) {
  int i = blockIdx.x * blockDim.x + threadIdx.x;
  if (i < E) atomicAdd(&g_deg[ei[E + i]], 1);   // dst row of edge_index
}

__global__ void k_scan(int n) {
  __shared__ int sums[1024];
  int t = threadIdx.x;
  int chunk = (n + 1023) / 1024;
  int b = t * chunk;
  int e = min(b + chunk, n);
  int s = 0;
  for (int i = b; i < e; i++) s += g_deg[i];
  sums[t] = s;
  __syncthreads();
  for (int o = 1; o < 1024; o <<= 1) {
    int v = (t >= o) ? sums[t - o] : 0;
    __syncthreads();
    sums[t] += v;
    __syncthreads();
  }
  int run = sums[t] - s;   // exclusive prefix
  for (int i = b; i < e; i++) { g_rp[i] = run; run += g_deg[i]; }
  if (t == 1023) g_rp[n] = sums[1023];
}

__global__ void k_scatter(const int* __restrict__ ei, int E, int n) {
  int i = blockIdx.x * blockDim.x + threadIdx.x;
  if (i >= E + n) return;
  int s, d;
  if (i < E) { s = ei[i]; d = ei[E + i]; } else { s = d = i - E; }
  int pos = atomicAdd(&g_fill[d], 1);
  g_csrc[g_rp[d] + pos] = s;
}

// ---------------- GEMM + fused attention dots -----------------------------------
// h[N,128] = X[N,fin] @ W[fin,128], then a_src/a_dst per node per head from the
// live accumulators. block = 128 threads, 32-row smem tile, 8 rows x 4 cols per
// thread, packed f32x2 FMAs (2 FMA/inst).
__global__ void k_gemm(const float* __restrict__ Xin, int insel,
                       const float* __restrict__ W,
                       const float* __restrict__ asrc,
                       const float* __restrict__ adst, int n, int fin) {
  const float* X = Xin ? Xin : (insel ? g_f1 : g_f0);
  __shared__ float xs[32 * 128];
  int tid = threadIdx.x;
  int lane = tid & 31;
  int row0 = blockIdx.x * 32;
  int fin4 = fin >> 2;
  int nf4 = 32 * fin4;
  const float4* X4 = (const float4*)X;
  for (int i = tid; i < nf4; i += 128) {
    int row = i / fin4;
    int kk = i - row * fin4;
    float4 v = make_float4(0.f, 0.f, 0.f, 0.f);
    if (row0 + row < n) v = X4[(row0 + row) * fin4 + kk];
    ((float4*)xs)[i] = v;
  }
  __syncthreads();
  int colg = lane;
  int rowseg = tid >> 5;
  unsigned long long acc[8][2];
#pragma unroll
  for (int r = 0; r < 8; r++) { acc[r][0] = 0ULL; acc[r][1] = 0ULL; }
  const float* xb = &xs[(rowseg * 8) * fin];
  const float* wb = &W[colg * 4];
  for (int k = 0; k < fin; k += 4) {
    ulonglong2 w0 = *(const ulonglong2*)&wb[(k + 0) * 128];
    ulonglong2 w1 = *(const ulonglong2*)&wb[(k + 1) * 128];
    ulonglong2 w2 = *(const ulonglong2*)&wb[(k + 2) * 128];
    ulonglong2 w3 = *(const ulonglong2*)&wb[(k + 3) * 128];
#pragma unroll
    for (int r = 0; r < 8; r++) {
      float4 x4 = *(const float4*)&xb[r * fin + k];
      unsigned long long xx;
      PACK2(xx, x4.x); FMA2(acc[r][0], xx, w0.x); FMA2(acc[r][1], xx, w0.y);
      PACK2(xx, x4.y); FMA2(acc[r][0], xx, w1.x); FMA2(acc[r][1], xx, w1.y);
      PACK2(xx, x4.z); FMA2(acc[r][0], xx, w2.x); FMA2(acc[r][1], xx, w2.y);
      PACK2(xx, x4.w); FMA2(acc[r][0], xx, w3.x); FMA2(acc[r][1], xx, w3.y);
    }
  }
  // epilogue: store h + compute attention dots per row
  float4 as4 = *(const float4*)&asrc[colg * 4];   // att layout [H*C]=[128] matches cols
  float4 ad4 = *(const float4*)&adst[colg * 4];
#pragma unroll
  for (int r = 0; r < 8; r++) {
    int row = row0 + rowseg * 8 + r;
    unsigned a, b, c, d;
    UNPACK2(a, b, acc[r][0]);
    UNPACK2(c, d, acc[r][1]);
    float4 hv = make_float4(__uint_as_float(a), __uint_as_float(b),
                            __uint_as_float(c), __uint_as_float(d));
    float ss = hv.x * as4.x + hv.y * as4.y + hv.z * as4.z + hv.w * as4.w;
    float sd = hv.x * ad4.x + hv.y * ad4.y + hv.z * ad4.z + hv.w * ad4.w;
#pragma unroll
    for (int o = 8; o; o >>= 1) {   // reduce within each 16-lane head half
      ss += __shfl_xor_sync(0xffffffffu, ss, o);
      sd += __shfl_xor_sync(0xffffffffu, sd, o);
    }
    float ss1 = __shfl_sync(0xffffffffu, ss, 16);
    float sd1 = __shfl_sync(0xffffffffu, sd, 16);
    if (row < n) {
      *(float4*)&g_h[row * 128 + colg * 4] = hv;
      if (lane == 0) *(float4*)&g_att[4 * row] = make_float4(ss, ss1, sd, sd1);
    }
  }
}

// ---------------- softmax + aggregate + head-mean + bias + relu ------------------
// one warp per destination node, single pass (no max subtraction: softmax is
// shift-invariant and logits are far from exp overflow). lane = one float4
// chunk of one head (lanes 0-15 head0, 16-31 head1); heads exchanged via shfl.
__global__ void k_agg(const float* __restrict__ bias, int outsel, int n) {
  float* OUT = outsel ? g_f1 : g_f0;
  int v = blockIdx.x * 8 + (threadIdx.x >> 5);
  int lane = threadIdx.x & 31;
  if (v >= n) return;
  int rs = g_rp[v], re = g_rp[v + 1];
  float2 adv = *(const float2*)&g_att[4 * v + 2];
  bool head1 = lane >= 16;
  const float4* H4 = (const float4*)g_h;

  float s0 = 0.f, s1 = 0.f;
  float4 acc = make_float4(0.f, 0.f, 0.f, 0.f);
  for (int j = rs; j < re; j++) {
    int s = g_csrc[j];                                  // warp-broadcast
    float2 as = *(const float2*)&g_att[4 * s];          // warp-broadcast
    float e0 = as.x + adv.x; e0 = fmaxf(e0, 0.2f * e0); // leaky relu
    float e1 = as.y + adv.y; e1 = fmaxf(e1, 0.2f * e1);
    float x0 = __expf(e0), x1 = __expf(e1);
    s0 += x0; s1 += x1;
    float xw = head1 ? x1 : x0;
    float4 hv = H4[s * 32 + lane];                      // one 128B line / lane
    acc.x += xw * hv.x; acc.y += xw * hv.y;
    acc.z += xw * hv.z; acc.w += xw * hv.w;
  }
  float r0 = 0.5f / fmaxf(s0, 1e-16f);
  float r1 = 0.5f / fmaxf(s1, 1e-16f);
  float rw = head1 ? r1 : r0;
  acc.x *= rw; acc.y *= rw; acc.z *= rw; acc.w *= rw;
  float px = __shfl_xor_sync(0xffffffffu, acc.x, 16);
  float py = __shfl_xor_sync(0xffffffffu, acc.y, 16);
  float pz = __shfl_xor_sync(0xffffffffu, acc.z, 16);
  float pw = __shfl_xor_sync(0xffffffffu, acc.w, 16);
  if (!head1) {
    float4 b4 = *(const float4*)&bias[lane * 4];
    float4 o;
    o.x = fmaxf(acc.x + px + b4.x, 0.f);
    o.y = fmaxf(acc.y + py + b4.y, 0.f);
    o.z = fmaxf(acc.z + pz + b4.z, 0.f);
    o.w = fmaxf(acc.w + pw + b4.w, 0.f);
    *(float4*)&OUT[v * 64 + lane * 4] = o;
  }
}

// ---------------- pooling + final linear -----------------------------------------
__global__ void k_pool(const float* __restrict__ lw, const int* __restrict__ batch, int n) {
  int v = blockIdx.x * 8 + (threadIdx.x >> 5);
  int lane = threadIdx.x & 31;
  if (v >= n) return;
  const float* fp = &g_f0[v * 64];
  float p = fp[lane] * lw[lane] + fp[lane + 32] * lw[lane + 32];
#pragma unroll
  for (int o = 16; o; o >>= 1) p += __shfl_xor_sync(0xffffffffu, p, o);
  if (lane == 0) {
    int b = batch[v];
    atomicAdd(&g_gsum[b], p);
    atomicAdd(&g_gcnt[b], 1.f);
  }
}

__global__ void k_final(const float* __restrict__ lb, float* __restrict__ out, int g) {
  int i = blockIdx.x * blockDim.x + threadIdx.x;
  if (i < g) out[i] = g_gsum[i] / fmaxf(g_gcnt[i], 1.f) + lb[0];
}

// ---------------- launch ----------------------------------------------------------
extern "C" void kernel_launch(void* const* d_in, const int* in_sizes, int n_in,
                              void* d_out, int out_size) {
  int base;
  const int *ei, *bat;
  int Esz;
  if (in_sizes[1] > 1000000) {          // dict order: x, edge_index, batch, ...
    ei = (const int*)d_in[1];
    bat = (const int*)d_in[2];
    base = 3;
    Esz = in_sizes[1];
  } else {                               // signature order
    base = 1;
    ei = (const int*)d_in[15];
    bat = (const int*)d_in[16];
    Esz = in_sizes[15];
  }
  const float* x   = (const float*)d_in[0];
  const float* W1  = (const float*)d_in[base + 0];
  const float* as1 = (const float*)d_in[base + 1];
  const float* ad1 = (const float*)d_in[base + 2];
  const float* b1  = (const float*)d_in[base + 3];
  const float* W2  = (const float*)d_in[base + 4];
  const float* as2 = (const float*)d_in[base + 5];
  const float* ad2 = (const float*)d_in[base + 6];
  const float* b2  = (const float*)d_in[base + 7];
  const float* W3  = (const float*)d_in[base + 8];
  const float* as3 = (const float*)d_in[base + 9];
  const float* ad3 = (const float*)d_in[base + 10];
  const float* b3  = (const float*)d_in[base + 11];
  const float* lw  = (const float*)d_in[base + 12];
  const float* lb  = (const float*)d_in[base + 13];

  int n = in_sizes[0] / 128;
  int E = Esz / 2;
  int G = out_size;

  const int tb = 256;
  k_init<<<(n + tb - 1) / tb, tb>>>(n, G);
  k_count<<<(E + tb - 1) / tb, tb>>>(ei, E);
  k_scan<<<1, 1024>>>(n);
  k_scatter<<<(E + n + tb - 1) / tb, tb>>>(ei, E, n);

  int gb = (n + 31) / 32;
  int wg = (n + 7) / 8;

  k_gemm<<<gb, 128>>>(x, 0, W1, as1, ad1, n, 128);
  k_agg<<<wg, 256>>>(b1, 0, n);
  k_gemm<<<gb, 128>>>(nullptr, 0, W2, as2, ad2, n, 64);
  k_agg<<<wg, 256>>>(b2, 1, n);
  k_gemm<<<gb, 128>>>(nullptr, 1, W3, as3, ad3, n, 64);
  k_agg<<<wg, 256>>>(b3, 0, n);

  k_pool<<<wg, 256>>>(lw, bat, n);
  k_final<<<(G + tb - 1) / tb, tb>>>(lb, (float*)d_out, G);
}

// round 3
// speedup vs baseline: 1.4068x; 1.0652x over previous
#include <cuda_runtime.h>
#include <cuda_fp16.h>

#define NMAX 50000
#define EMAX 800000
#define GMAX 2500
#define ETOT (EMAX + NMAX)

// packed dual-fp32 helpers (sm_100+ PTX)
#define PACK2(out, f) asm("mov.b64 %0, {%1, %1};" : "=l"(out) : "r"(__float_as_uint(f)))
#define FMA2(d, a, b) asm("fma.rn.f32x2 %0, %1, %2, %0;" : "+l"(d) : "l"(a), "l"(b))
#define UNPACK2(lo, hi, v) asm("mov.b64 {%0, %1}, %2;" : "=r"(lo), "=r"(hi) : "l"(v))

// ---------------- scratch (device globals; no allocation allowed) ----------------
__device__ uint2 g_h16[NMAX * 32];     // per-layer hidden, fp16: [N][32 lanes x 4 half]
__device__ float g_f0[NMAX * 64];      // layer output ping (fp32)
__device__ float g_f1[NMAX * 64];      // layer output pong
__device__ float g_att[NMAX * 4];      // per node: a_src0, a_src1, a_dst0, a_dst1
__device__ int   g_rp[NMAX + 1];       // CSR row_ptr by dst
__device__ int   g_deg[NMAX];
__device__ int   g_fill[NMAX];
__device__ int   g_csrc[ETOT];         // CSR src indices
__device__ float g_gsum[GMAX];
__device__ float g_gcnt[GMAX];

// ---------------- CSR build (dst is layer-invariant) + pool zeroing --------------
__global__ void k_init(int n, int g) {
  int i = blockIdx.x * blockDim.x + threadIdx.x;
  if (i < n) { g_deg[i] = 1; g_fill[i] = 0; }   // 1 = self loop
  if (i < g) { g_gsum[i] = 0.f; g_gcnt[i] = 0.f; }
}

__global__ void k_count(const int* __restrict__ ei, int E) {
  int i = blockIdx.x * blockDim.x + threadIdx.x;
  if (i < E) atomicAdd(&g_deg[ei[E + i]], 1);   // dst row of edge_index
}

__global__ void k_scan(int n) {
  __shared__ int sums[1024];
  int t = threadIdx.x;
  int chunk = (n + 1023) / 1024;
  int b = t * chunk;
  int e = min(b + chunk, n);
  int s = 0;
  for (int i = b; i < e; i++) s += g_deg[i];
  sums[t] = s;
  __syncthreads();
  for (int o = 1; o < 1024; o <<= 1) {
    int v = (t >= o) ? sums[t - o] : 0;
    __syncthreads();
    sums[t] += v;
    __syncthreads();
  }
  int run = sums[t] - s;   // exclusive prefix
  for (int i = b; i < e; i++) { g_rp[i] = run; run += g_deg[i]; }
  if (t == 1023) g_rp[n] = sums[1023];
}

__global__ void k_scatter(const int* __restrict__ ei, int E, int n) {
  int i = blockIdx.x * blockDim.x + threadIdx.x;
  if (i >= E + n) return;
  int s, d;
  if (i < E) { s = ei[i]; d = ei[E + i]; } else { s = d = i - E; }
  int pos = atomicAdd(&g_fill[d], 1);
  g_csrc[g_rp[d] + pos] = s;
}

// ---------------- GEMM + fused attention dots -----------------------------------
// h[N,128] = X[N,fin] @ W[fin,128]; attention dots from live fp32 accumulators;
// h stored fp16 (message payload only). block = 128 thr, 32-row tile, f32x2 FMAs.
__global__ void k_gemm(const float* __restrict__ Xin, int insel,
                       const float* __restrict__ W,
                       const float* __restrict__ asrc,
                       const float* __restrict__ adst, int n, int fin) {
  const float* X = Xin ? Xin : (insel ? g_f1 : g_f0);
  __shared__ float xs[32 * 128];
  int tid = threadIdx.x;
  int lane = tid & 31;
  int row0 = blockIdx.x * 32;
  int fin4 = fin >> 2;
  int nf4 = 32 * fin4;
  const float4* X4 = (const float4*)X;
  for (int i = tid; i < nf4; i += 128) {
    int row = i / fin4;
    int kk = i - row * fin4;
    float4 v = make_float4(0.f, 0.f, 0.f, 0.f);
    if (row0 + row < n) v = X4[(row0 + row) * fin4 + kk];
    ((float4*)xs)[i] = v;
  }
  __syncthreads();
  int colg = lane;
  int rowseg = tid >> 5;
  unsigned long long acc[8][2];
#pragma unroll
  for (int r = 0; r < 8; r++) { acc[r][0] = 0ULL; acc[r][1] = 0ULL; }
  const float* xb = &xs[(rowseg * 8) * fin];
  const float* wb = &W[colg * 4];
  for (int k = 0; k < fin; k += 4) {
    ulonglong2 w0 = *(const ulonglong2*)&wb[(k + 0) * 128];
    ulonglong2 w1 = *(const ulonglong2*)&wb[(k + 1) * 128];
    ulonglong2 w2 = *(const ulonglong2*)&wb[(k + 2) * 128];
    ulonglong2 w3 = *(const ulonglong2*)&wb[(k + 3) * 128];
#pragma unroll
    for (int r = 0; r < 8; r++) {
      float4 x4 = *(const float4*)&xb[r * fin + k];
      unsigned long long xx;
      PACK2(xx, x4.x); FMA2(acc[r][0], xx, w0.x); FMA2(acc[r][1], xx, w0.y);
      PACK2(xx, x4.y); FMA2(acc[r][0], xx, w1.x); FMA2(acc[r][1], xx, w1.y);
      PACK2(xx, x4.z); FMA2(acc[r][0], xx, w2.x); FMA2(acc[r][1], xx, w2.y);
      PACK2(xx, x4.w); FMA2(acc[r][0], xx, w3.x); FMA2(acc[r][1], xx, w3.y);
    }
  }
  // epilogue: attention dots (fp32 exact) + fp16 h store
  float4 as4 = *(const float4*)&asrc[colg * 4];   // att layout [H*C]=[128] matches cols
  float4 ad4 = *(const float4*)&adst[colg * 4];
#pragma unroll
  for (int r = 0; r < 8; r++) {
    int row = row0 + rowseg * 8 + r;
    unsigned a, b, c, d;
    UNPACK2(a, b, acc[r][0]);
    UNPACK2(c, d, acc[r][1]);
    float4 hv = make_float4(__uint_as_float(a), __uint_as_float(b),
                            __uint_as_float(c), __uint_as_float(d));
    float ss = hv.x * as4.x + hv.y * as4.y + hv.z * as4.z + hv.w * as4.w;
    float sd = hv.x * ad4.x + hv.y * ad4.y + hv.z * ad4.z + hv.w * ad4.w;
#pragma unroll
    for (int o = 8; o; o >>= 1) {   // reduce within each 16-lane head half
      ss += __shfl_xor_sync(0xffffffffu, ss, o);
      sd += __shfl_xor_sync(0xffffffffu, sd, o);
    }
    float ss1 = __shfl_sync(0xffffffffu, ss, 16);
    float sd1 = __shfl_sync(0xffffffffu, sd, 16);
    if (row < n) {
      half2 p0 = __floats2half2_rn(hv.x, hv.y);
      half2 p1 = __floats2half2_rn(hv.z, hv.w);
      uint2 hp;
      hp.x = *(unsigned*)&p0;
      hp.y = *(unsigned*)&p1;
      g_h16[row * 32 + colg] = hp;
      if (lane == 0) *(float4*)&g_att[4 * row] = make_float4(ss, ss1, sd, sd1);
    }
  }
}

// ---------------- softmax + aggregate + head-mean + bias + relu ------------------
// one warp per destination node, single pass (softmax shift-invariance: logits are
// far from exp overflow, so no max pass). lane = 4 fp16 channels of one head
// (lanes 0-15 head0, 16-31 head1); 8B/lane = 256B/edge gather.
__global__ void k_agg(const float* __restrict__ bias, int outsel, int n) {
  float* OUT = outsel ? g_f1 : g_f0;
  int v = blockIdx.x * 8 + (threadIdx.x >> 5);
  int lane = threadIdx.x & 31;
  if (v >= n) return;
  int rs = g_rp[v], re = g_rp[v + 1];
  float2 adv = *(const float2*)&g_att[4 * v + 2];
  bool head1 = lane >= 16;

  float s0 = 0.f, s1 = 0.f;
  float4 acc = make_float4(0.f, 0.f, 0.f, 0.f);
#pragma unroll 2
  for (int j = rs; j < re; j++) {
    int s = g_csrc[j];                                  // warp-broadcast
    float2 as = *(const float2*)&g_att[4 * s];          // warp-broadcast
    uint2 hp = g_h16[s * 32 + lane];                    // 256B/warp gather
    float e0 = as.x + adv.x; e0 = fmaxf(e0, 0.2f * e0); // leaky relu
    float e1 = as.y + adv.y; e1 = fmaxf(e1, 0.2f * e1);
    float x0 = __expf(e0), x1 = __expf(e1);
    s0 += x0; s1 += x1;
    float xw = head1 ? x1 : x0;
    float2 f0 = __half22float2(*(half2*)&hp.x);
    float2 f1 = __half22float2(*(half2*)&hp.y);
    acc.x += xw * f0.x; acc.y += xw * f0.y;
    acc.z += xw * f1.x; acc.w += xw * f1.y;
  }
  float r0 = 0.5f / fmaxf(s0, 1e-16f);
  float r1 = 0.5f / fmaxf(s1, 1e-16f);
  float rw = head1 ? r1 : r0;
  acc.x *= rw; acc.y *= rw; acc.z *= rw; acc.w *= rw;
  float px = __shfl_xor_sync(0xffffffffu, acc.x, 16);
  float py = __shfl_xor_sync(0xffffffffu, acc.y, 16);
  float pz = __shfl_xor_sync(0xffffffffu, acc.z, 16);
  float pw = __shfl_xor_sync(0xffffffffu, acc.w, 16);
  if (!head1) {
    float4 b4 = *(const float4*)&bias[lane * 4];
    float4 o;
    o.x = fmaxf(acc.x + px + b4.x, 0.f);
    o.y = fmaxf(acc.y + py + b4.y, 0.f);
    o.z = fmaxf(acc.z + pz + b4.z, 0.f);
    o.w = fmaxf(acc.w + pw + b4.w, 0.f);
    *(float4*)&OUT[v * 64 + lane * 4] = o;
  }
}

// ---------------- pooling + final linear -----------------------------------------
__global__ void k_pool(const float* __restrict__ lw, const int* __restrict__ batch, int n) {
  int v = blockIdx.x * 8 + (threadIdx.x >> 5);
  int lane = threadIdx.x & 31;
  if (v >= n) return;
  const float* fp = &g_f0[v * 64];
  float p = fp[lane] * lw[lane] + fp[lane + 32] * lw[lane + 32];
#pragma unroll
  for (int o = 16; o; o >>= 1) p += __shfl_xor_sync(0xffffffffu, p, o);
  if (lane == 0) {
    int b = batch[v];
    atomicAdd(&g_gsum[b], p);
    atomicAdd(&g_gcnt[b], 1.f);
  }
}

__global__ void k_final(const float* __restrict__ lb, float* __restrict__ out, int g) {
  int i = blockIdx.x * blockDim.x + threadIdx.x;
  if (i < g) out[i] = g_gsum[i] / fmaxf(g_gcnt[i], 1.f) + lb[0];
}

// ---------------- launch ----------------------------------------------------------
extern "C" void kernel_launch(void* const* d_in, const int* in_sizes, int n_in,
                              void* d_out, int out_size) {
  int base;
  const int *ei, *bat;
  int Esz;
  if (in_sizes[1] > 1000000) {          // dict order: x, edge_index, batch, ...
    ei = (const int*)d_in[1];
    bat = (const int*)d_in[2];
    base = 3;
    Esz = in_sizes[1];
  } else {                               // signature order
    base = 1;
    ei = (const int*)d_in[15];
    bat = (const int*)d_in[16];
    Esz = in_sizes[15];
  }
  const float* x   = (const float*)d_in[0];
  const float* W1  = (const float*)d_in[base + 0];
  const float* as1 = (const float*)d_in[base + 1];
  const float* ad1 = (const float*)d_in[base + 2];
  const float* b1  = (const float*)d_in[base + 3];
  const float* W2  = (const float*)d_in[base + 4];
  const float* as2 = (const float*)d_in[base + 5];
  const float* ad2 = (const float*)d_in[base + 6];
  const float* b2  = (const float*)d_in[base + 7];
  const float* W3  = (const float*)d_in[base + 8];
  const float* as3 = (const float*)d_in[base + 9];
  const float* ad3 = (const float*)d_in[base + 10];
  const float* b3  = (const float*)d_in[base + 11];
  const float* lw  = (const float*)d_in[base + 12];
  const float* lb  = (const float*)d_in[base + 13];

  int n = in_sizes[0] / 128;
  int E = Esz / 2;
  int G = out_size;

  const int tb = 256;
  k_init<<<(n + tb - 1) / tb, tb>>>(n, G);
  k_count<<<(E + tb - 1) / tb, tb>>>(ei, E);
  k_scan<<<1, 1024>>>(n);
  k_scatter<<<(E + n + tb - 1) / tb, tb>>>(ei, E, n);

  int gb = (n + 31) / 32;
  int wg = (n + 7) / 8;

  k_gemm<<<gb, 128>>>(x, 0, W1, as1, ad1, n, 128);
  k_agg<<<wg, 256>>>(b1, 0, n);
  k_gemm<<<gb, 128>>>(nullptr, 0, W2, as2, ad2, n, 64);
  k_agg<<<wg, 256>>>(b2, 1, n);
  k_gemm<<<gb, 128>>>(nullptr, 1, W3, as3, ad3, n, 64);
  k_agg<<<wg, 256>>>(b3, 0, n);

  k_pool<<<wg, 256>>>(lw, bat, n);
  k_final<<<(G + tb - 1) / tb, tb>>>(lb, (float*)d_out, G);
}

// round 4
// speedup vs baseline: 1.5307x; 1.0880x over previous
#include <cuda_runtime.h>
#include <cuda_fp16.h>

#define NMAX 50000
#define EMAX 800000
#define GMAX 2500
#define ETOT (EMAX + NMAX)

// packed dual-fp32 helpers (sm_100+ PTX)
#define PACK2(out, f) asm("mov.b64 %0, {%1, %1};" : "=l"(out) : "r"(__float_as_uint(f)))
#define FMA2(d, a, b) asm("fma.rn.f32x2 %0, %1, %2, %0;" : "+l"(d) : "l"(a), "l"(b))
#define UNPACK2(lo, hi, v) asm("mov.b64 {%0, %1}, %2;" : "=r"(lo), "=r"(hi) : "l"(v))

// ---------------- scratch (device globals; no allocation allowed) ----------------
__device__ uint2 g_h16[NMAX * 32];     // per-layer hidden, fp16: [N][32 lanes x 4 half]
__device__ float g_f0[NMAX * 64];      // layer output ping (fp32)
__device__ float g_f1[NMAX * 64];      // layer output pong
__device__ float g_att[NMAX * 4];      // per node: a_src0, a_src1, a_dst0, a_dst1
__device__ int   g_rp[NMAX + 1];       // CSR row_ptr by dst
__device__ int   g_deg[NMAX];
__device__ int   g_fill[NMAX];
__device__ int   g_csrc[ETOT];         // CSR src indices
__device__ float g_gsum[GMAX];
__device__ float g_gcnt[GMAX];

// ---------------- CSR build (dst is layer-invariant) + pool zeroing --------------
__global__ void k_init(int n, int g) {
  int i = blockIdx.x * blockDim.x + threadIdx.x;
  if (i < n) { g_deg[i] = 1; g_fill[i] = 0; }   // 1 = self loop
  if (i < g) { g_gsum[i] = 0.f; g_gcnt[i] = 0.f; }
}

__global__ void k_count(const int* __restrict__ ei, int E) {
  int i = blockIdx.x * blockDim.x + threadIdx.x;
  if (i < E) atomicAdd(&g_deg[ei[E + i]], 1);   // dst row of edge_index
}

__global__ void k_scan(int n) {
  __shared__ int sums[1024];
  int t = threadIdx.x;
  int chunk = (n + 1023) / 1024;
  int b = t * chunk;
  int e = min(b + chunk, n);
  int s = 0;
  for (int i = b; i < e; i++) s += g_deg[i];
  sums[t] = s;
  __syncthreads();
  for (int o = 1; o < 1024; o <<= 1) {
    int v = (t >= o) ? sums[t - o] : 0;
    __syncthreads();
    sums[t] += v;
    __syncthreads();
  }
  int run = sums[t] - s;   // exclusive prefix
  for (int i = b; i < e; i++) { g_rp[i] = run; run += g_deg[i]; }
  if (t == 1023) g_rp[n] = sums[1023];
}

__global__ void k_scatter(const int* __restrict__ ei, int E, int n) {
  int i = blockIdx.x * blockDim.x + threadIdx.x;
  if (i >= E + n) return;
  int s, d;
  if (i < E) { s = ei[i]; d = ei[E + i]; } else { s = d = i - E; }
  int pos = atomicAdd(&g_fill[d], 1);
  g_csrc[g_rp[d] + pos] = s;
}

// ---------------- GEMM + fused attention dots -----------------------------------
// h[N,128] = X[N,fin] @ W[fin,128]; attention dots from live fp32 accumulators;
// h stored fp16 (message payload only). block = 128 thr, 32-row tile, f32x2 FMAs.
__global__ void k_gemm(const float* __restrict__ Xin, int insel,
                       const float* __restrict__ W,
                       const float* __restrict__ asrc,
                       const float* __restrict__ adst, int n, int fin) {
  const float* X = Xin ? Xin : (insel ? g_f1 : g_f0);
  __shared__ float xs[32 * 128];
  int tid = threadIdx.x;
  int lane = tid & 31;
  int row0 = blockIdx.x * 32;
  int fin4 = fin >> 2;
  int nf4 = 32 * fin4;
  const float4* X4 = (const float4*)X;
  for (int i = tid; i < nf4; i += 128) {
    int row = i / fin4;
    int kk = i - row * fin4;
    float4 v = make_float4(0.f, 0.f, 0.f, 0.f);
    if (row0 + row < n) v = X4[(row0 + row) * fin4 + kk];
    ((float4*)xs)[i] = v;
  }
  __syncthreads();
  int colg = lane;
  int rowseg = tid >> 5;
  unsigned long long acc[8][2];
#pragma unroll
  for (int r = 0; r < 8; r++) { acc[r][0] = 0ULL; acc[r][1] = 0ULL; }
  const float* xb = &xs[(rowseg * 8) * fin];
  const float* wb = &W[colg * 4];
  for (int k = 0; k < fin; k += 4) {
    ulonglong2 w0 = *(const ulonglong2*)&wb[(k + 0) * 128];
    ulonglong2 w1 = *(const ulonglong2*)&wb[(k + 1) * 128];
    ulonglong2 w2 = *(const ulonglong2*)&wb[(k + 2) * 128];
    ulonglong2 w3 = *(const ulonglong2*)&wb[(k + 3) * 128];
#pragma unroll
    for (int r = 0; r < 8; r++) {
      float4 x4 = *(const float4*)&xb[r * fin + k];
      unsigned long long xx;
      PACK2(xx, x4.x); FMA2(acc[r][0], xx, w0.x); FMA2(acc[r][1], xx, w0.y);
      PACK2(xx, x4.y); FMA2(acc[r][0], xx, w1.x); FMA2(acc[r][1], xx, w1.y);
      PACK2(xx, x4.z); FMA2(acc[r][0], xx, w2.x); FMA2(acc[r][1], xx, w2.y);
      PACK2(xx, x4.w); FMA2(acc[r][0], xx, w3.x); FMA2(acc[r][1], xx, w3.y);
    }
  }
  // epilogue: attention dots (fp32 exact) + fp16 h store
  float4 as4 = *(const float4*)&asrc[colg * 4];   // att layout [H*C]=[128] matches cols
  float4 ad4 = *(const float4*)&adst[colg * 4];
#pragma unroll
  for (int r = 0; r < 8; r++) {
    int row = row0 + rowseg * 8 + r;
    unsigned a, b, c, d;
    UNPACK2(a, b, acc[r][0]);
    UNPACK2(c, d, acc[r][1]);
    float4 hv = make_float4(__uint_as_float(a), __uint_as_float(b),
                            __uint_as_float(c), __uint_as_float(d));
    float ss = hv.x * as4.x + hv.y * as4.y + hv.z * as4.z + hv.w * as4.w;
    float sd = hv.x * ad4.x + hv.y * ad4.y + hv.z * ad4.z + hv.w * ad4.w;
#pragma unroll
    for (int o = 8; o; o >>= 1) {   // reduce within each 16-lane head half
      ss += __shfl_xor_sync(0xffffffffu, ss, o);
      sd += __shfl_xor_sync(0xffffffffu, sd, o);
    }
    float ss1 = __shfl_sync(0xffffffffu, ss, 16);
    float sd1 = __shfl_sync(0xffffffffu, sd, 16);
    if (row < n) {
      half2 p0 = __floats2half2_rn(hv.x, hv.y);
      half2 p1 = __floats2half2_rn(hv.z, hv.w);
      uint2 hp;
      hp.x = *(unsigned*)&p0;
      hp.y = *(unsigned*)&p1;
      g_h16[row * 32 + colg] = hp;
      if (lane == 0) *(float4*)&g_att[4 * row] = make_float4(ss, ss1, sd, sd1);
    }
  }
}

// ---------------- softmax + aggregate + head-mean + bias + relu ------------------
// one warp per destination node, phase-split:
//   phase A (lane-parallel, chunk of 32 edges): coalesced csrc load, att gather,
//           leakyrelu+exp per lane, softmax-sum accumulation.
//   phase B (serial over chunk, lanes = channels): indices/weights come from
//           registers via shfl, so the only memory op is ONE independent 8B/lane
//           h-gather per edge -> unroll gives 4+ loads in flight (was a 2-hop
//           dependent L2 chain). No max pass (shift-invariance; logits small).
__global__ void k_agg(const float* __restrict__ bias, int outsel, int n) {
  float* OUT = outsel ? g_f1 : g_f0;
  int v = blockIdx.x * 8 + (threadIdx.x >> 5);
  int lane = threadIdx.x & 31;
  if (v >= n) return;
  int rs = g_rp[v], re = g_rp[v + 1];
  float2 adv = *(const float2*)&g_att[4 * v + 2];
  bool head1 = lane >= 16;

  float s0 = 0.f, s1 = 0.f;
  float4 acc = make_float4(0.f, 0.f, 0.f, 0.f);
  for (int base = rs; base < re; base += 32) {
    int jj = base + lane;
    int s_l = 0;
    float x0 = 0.f, x1 = 0.f;
    if (jj < re) {
      s_l = g_csrc[jj];                                 // coalesced
      float2 as = *(const float2*)&g_att[4 * s_l];      // independent gathers
      float e0 = as.x + adv.x; e0 = fmaxf(e0, 0.2f * e0);
      float e1 = as.y + adv.y; e1 = fmaxf(e1, 0.2f * e1);
      x0 = __expf(e0); x1 = __expf(e1);
    }
    s0 += x0; s1 += x1;
    int cnt = min(re - base, 32);
#pragma unroll 4
    for (int k = 0; k < cnt; k++) {
      int s = __shfl_sync(0xffffffffu, s_l, k);
      float xa = __shfl_sync(0xffffffffu, x0, k);
      float xb = __shfl_sync(0xffffffffu, x1, k);
      float xw = head1 ? xb : xa;
      uint2 hp = g_h16[s * 32 + lane];                  // independent 256B/warp
      float2 f0 = __half22float2(*(half2*)&hp.x);
      float2 f1 = __half22float2(*(half2*)&hp.y);
      acc.x += xw * f0.x; acc.y += xw * f0.y;
      acc.z += xw * f1.x; acc.w += xw * f1.y;
    }
  }
#pragma unroll
  for (int o = 16; o; o >>= 1) {
    s0 += __shfl_xor_sync(0xffffffffu, s0, o);
    s1 += __shfl_xor_sync(0xffffffffu, s1, o);
  }
  float r0 = 0.5f / fmaxf(s0, 1e-16f);
  float r1 = 0.5f / fmaxf(s1, 1e-16f);
  float rw = head1 ? r1 : r0;
  acc.x *= rw; acc.y *= rw; acc.z *= rw; acc.w *= rw;
  float px = __shfl_xor_sync(0xffffffffu, acc.x, 16);
  float py = __shfl_xor_sync(0xffffffffu, acc.y, 16);
  float pz = __shfl_xor_sync(0xffffffffu, acc.z, 16);
  float pw = __shfl_xor_sync(0xffffffffu, acc.w, 16);
  if (!head1) {
    float4 b4 = *(const float4*)&bias[lane * 4];
    float4 o;
    o.x = fmaxf(acc.x + px + b4.x, 0.f);
    o.y = fmaxf(acc.y + py + b4.y, 0.f);
    o.z = fmaxf(acc.z + pz + b4.z, 0.f);
    o.w = fmaxf(acc.w + pw + b4.w, 0.f);
    *(float4*)&OUT[v * 64 + lane * 4] = o;
  }
}

// ---------------- pooling + final linear -----------------------------------------
__global__ void k_pool(const float* __restrict__ lw, const int* __restrict__ batch, int n) {
  int v = blockIdx.x * 8 + (threadIdx.x >> 5);
  int lane = threadIdx.x & 31;
  if (v >= n) return;
  const float* fp = &g_f0[v * 64];
  float p = fp[lane] * lw[lane] + fp[lane + 32] * lw[lane + 32];
#pragma unroll
  for (int o = 16; o; o >>= 1) p += __shfl_xor_sync(0xffffffffu, p, o);
  if (lane == 0) {
    int b = batch[v];
    atomicAdd(&g_gsum[b], p);
    atomicAdd(&g_gcnt[b], 1.f);
  }
}

__global__ void k_final(const float* __restrict__ lb, float* __restrict__ out, int g) {
  int i = blockIdx.x * blockDim.x + threadIdx.x;
  if (i < g) out[i] = g_gsum[i] / fmaxf(g_gcnt[i], 1.f) + lb[0];
}

// ---------------- launch ----------------------------------------------------------
extern "C" void kernel_launch(void* const* d_in, const int* in_sizes, int n_in,
                              void* d_out, int out_size) {
  int base;
  const int *ei, *bat;
  int Esz;
  if (in_sizes[1] > 1000000) {          // dict order: x, edge_index, batch, ...
    ei = (const int*)d_in[1];
    bat = (const int*)d_in[2];
    base = 3;
    Esz = in_sizes[1];
  } else {                               // signature order
    base = 1;
    ei = (const int*)d_in[15];
    bat = (const int*)d_in[16];
    Esz = in_sizes[15];
  }
  const float* x   = (const float*)d_in[0];
  const float* W1  = (const float*)d_in[base + 0];
  const float* as1 = (const float*)d_in[base + 1];
  const float* ad1 = (const float*)d_in[base + 2];
  const float* b1  = (const float*)d_in[base + 3];
  const float* W2  = (const float*)d_in[base + 4];
  const float* as2 = (const float*)d_in[base + 5];
  const float* ad2 = (const float*)d_in[base + 6];
  const float* b2  = (const float*)d_in[base + 7];
  const float* W3  = (const float*)d_in[base + 8];
  const float* as3 = (const float*)d_in[base + 9];
  const float* ad3 = (const float*)d_in[base + 10];
  const float* b3  = (const float*)d_in[base + 11];
  const float* lw  = (const float*)d_in[base + 12];
  const float* lb  = (const float*)d_in[base + 13];

  int n = in_sizes[0] / 128;
  int E = Esz / 2;
  int G = out_size;

  const int tb = 256;
  k_init<<<(n + tb - 1) / tb, tb>>>(n, G);
  k_count<<<(E + tb - 1) / tb, tb>>>(ei, E);
  k_scan<<<1, 1024>>>(n);
  k_scatter<<<(E + n + tb - 1) / tb, tb>>>(ei, E, n);

  int gb = (n + 31) / 32;
  int wg = (n + 7) / 8;

  k_gemm<<<gb, 128>>>(x, 0, W1, as1, ad1, n, 128);
  k_agg<<<wg, 256>>>(b1, 0, n);
  k_gemm<<<gb, 128>>>(nullptr, 0, W2, as2, ad2, n, 64);
  k_agg<<<wg, 256>>>(b2, 1, n);
  k_gemm<<<gb, 128>>>(nullptr, 1, W3, as3, ad3, n, 64);
  k_agg<<<wg, 256>>>(b3, 0, n);

  k_pool<<<wg, 256>>>(lw, bat, n);
  k_final<<<(G + tb - 1) / tb, tb>>>(lb, (float*)d_out, G);
}